// round 2
// baseline (speedup 1.0000x reference)
#include <cuda_runtime.h>
#include <math.h>

// Problem constants
#define TT 512
#define BB 64
#define II 1024
#define HH 1024
#define GG 4096           // 4*H
#define NCTA 128          // persistent CTAs (1 per SM)
#define PTHREADS 256

// ---------------------------------------------------------------------------
// Device-global scratch (no allocations allowed at runtime)
// ---------------------------------------------------------------------------
__device__ __align__(16) float g_xproj[(size_t)TT * BB * GG]; // 512 MB
__device__ __align__(16) float g_h[2][BB * HH];               // h double buffer
__device__ unsigned g_bar_count = 0;
__device__ unsigned g_bar_gen   = 0;

__device__ __forceinline__ float sigf(float x) { return 1.f / (1.f + __expf(-x)); }

// ---------------------------------------------------------------------------
// Grid-wide barrier (sense via monotonically increasing generation counter).
// All NCTA CTAs are co-resident (1 per SM), so spinning is safe.
// ---------------------------------------------------------------------------
__device__ __forceinline__ void grid_barrier()
{
    __syncthreads();
    if (threadIdx.x == 0) {
        unsigned target = *(volatile unsigned*)&g_bar_gen + 1u;
        __threadfence();
        unsigned old = atomicAdd(&g_bar_count, 1u);
        if (old == NCTA - 1u) {
            g_bar_count = 0u;
            __threadfence();
            atomicExch(&g_bar_gen, target);
        } else {
            while ((int)(*(volatile unsigned*)&g_bar_gen - target) < 0)
                __nanosleep(64);
        }
        __threadfence();
    }
    __syncthreads();
}

// ---------------------------------------------------------------------------
// Kernel 1: x_proj[T*B, 4H] = x[T*B, I] @ W_ih^T + (b_ih + b_hh)
// CTA tile 64x64, K-chunks of 32, 256 threads, 4x4 register tiles,
// register prefetch double-buffering. Grid (4096/64, 32768/64) = (64, 512).
// ---------------------------------------------------------------------------
#define XAS 68   // padded smem row stride (floats); 68*4 = 272 B, 16B-aligned

__global__ __launch_bounds__(256) void xproj_gemm(
    const float* __restrict__ x,     // [T*B, I]
    const float* __restrict__ Wih,   // [4H, I]
    const float* __restrict__ bih,   // [4H]
    const float* __restrict__ bhh)   // [4H]
{
    __shared__ __align__(16) float As[32 * XAS];
    __shared__ __align__(16) float Bs[32 * XAS];

    const int tid = threadIdx.x;
    const int n0  = blockIdx.x * 64;
    const int m0  = blockIdx.y * 64;
    const int ty  = tid >> 4;   // 0..15 -> m = ty*4
    const int tx  = tid & 15;   // 0..15 -> n = tx*4

    const float* Ab = x   + (size_t)m0 * II;
    const float* Bb = Wih + (size_t)n0 * II;

    float acc[4][4];
#pragma unroll
    for (int i = 0; i < 4; i++)
#pragma unroll
        for (int j = 0; j < 4; j++) acc[i][j] = 0.f;

    // Prefetch first K-chunk into registers.
    float4 ra[2], rb[2];
#pragma unroll
    for (int i = 0; i < 2; i++) {
        int s = tid + i * 256; int r = s >> 3, cc = s & 7;   // r:0..63 cc:0..7
        ra[i] = *reinterpret_cast<const float4*>(Ab + (size_t)r * II + cc * 4);
        rb[i] = *reinterpret_cast<const float4*>(Bb + (size_t)r * II + cc * 4);
    }

    for (int k0 = 0; k0 < II; k0 += 32) {
        __syncthreads();
#pragma unroll
        for (int i = 0; i < 2; i++) {
            int s = tid + i * 256; int r = s >> 3, cc = s & 7;
            As[(cc * 4 + 0) * XAS + r] = ra[i].x;
            As[(cc * 4 + 1) * XAS + r] = ra[i].y;
            As[(cc * 4 + 2) * XAS + r] = ra[i].z;
            As[(cc * 4 + 3) * XAS + r] = ra[i].w;
            Bs[(cc * 4 + 0) * XAS + r] = rb[i].x;
            Bs[(cc * 4 + 1) * XAS + r] = rb[i].y;
            Bs[(cc * 4 + 2) * XAS + r] = rb[i].z;
            Bs[(cc * 4 + 3) * XAS + r] = rb[i].w;
        }
        __syncthreads();

        if (k0 + 32 < II) {
#pragma unroll
            for (int i = 0; i < 2; i++) {
                int s = tid + i * 256; int r = s >> 3, cc = s & 7;
                ra[i] = *reinterpret_cast<const float4*>(
                    Ab + (size_t)r * II + (k0 + 32) + cc * 4);
                rb[i] = *reinterpret_cast<const float4*>(
                    Bb + (size_t)r * II + (k0 + 32) + cc * 4);
            }
        }

#pragma unroll
        for (int kk = 0; kk < 32; kk++) {
            float4 av = *reinterpret_cast<const float4*>(As + kk * XAS + ty * 4);
            float4 bv = *reinterpret_cast<const float4*>(Bs + kk * XAS + tx * 4);
            float a4[4] = {av.x, av.y, av.z, av.w};
            float b4[4] = {bv.x, bv.y, bv.z, bv.w};
#pragma unroll
            for (int i = 0; i < 4; i++)
#pragma unroll
                for (int j = 0; j < 4; j++)
                    acc[i][j] += a4[i] * b4[j];
        }
    }

    const int n = n0 + tx * 4;
    float b0 = bih[n + 0] + bhh[n + 0];
    float b1 = bih[n + 1] + bhh[n + 1];
    float b2 = bih[n + 2] + bhh[n + 2];
    float b3 = bih[n + 3] + bhh[n + 3];
#pragma unroll
    for (int i = 0; i < 4; i++) {
        float4 v = make_float4(acc[i][0] + b0, acc[i][1] + b1,
                               acc[i][2] + b2, acc[i][3] + b3);
        *reinterpret_cast<float4*>(
            &g_xproj[(size_t)(m0 + ty * 4 + i) * GG + n]) = v;
    }
}

// ---------------------------------------------------------------------------
// Kernel 2: persistent recurrence. 128 CTAs x 256 threads.
// CTA bk owns j-indices [bk*8, bk*8+8) and the 32 gate columns
//   { g*1024 + bk*8 + jj : g in 0..3, jj in 0..7 }.
// Its 32x1024 W_hh slice is loaded into SMEM once and kept for all steps.
// Per step: gates(64x32) = h_prev(64x1024) @ Wslice^T + xproj[t] slice,
// computed with a 2-way K-split (two 128-thread groups), then the CTA-local
// pointwise cell update. c-state lives in SMEM. h is double-buffered globally.
// ---------------------------------------------------------------------------
#define PAS 68                      // padded As row stride
#define OFF_BS   0                  // W slice  [1024][32]   -> 32768 floats
#define OFF_AS   32768              // As[2][32][PAS]        ->  4352 floats
#define OFF_RED  (32768 + 2*32*PAS) // Red[64][32]           ->  2048 floats
#define OFF_GS   (OFF_RED + 2048)   // Gs[4][64][8]          ->  2048 floats
#define OFF_CS   (OFF_GS + 2048)    // Cs[64][8]             ->   512 floats
#define SMEM_FLOATS (OFF_CS + 512)
#define SMEM_BYTES  (SMEM_FLOATS * 4)

__global__ __launch_bounds__(PTHREADS) void lstm_persist(
    const float* __restrict__ Whh,   // [4H, H]
    float* __restrict__ out)         // [T*B*H + 2*B*H]
{
    extern __shared__ __align__(16) float smem[];
    float* Bs  = smem + OFF_BS;
    float* Red = smem + OFF_RED;
    float* Gs  = smem + OFF_GS;
    float* Cs  = smem + OFF_CS;

    const int tid = threadIdx.x;
    const int bk  = blockIdx.x;      // 0..127

    // Load this CTA's 32 W_hh rows into SMEM as Bs[k][c] (c = gate column id).
    for (int i = tid; i < 32 * 1024; i += PTHREADS) {
        int k = i & 1023, c = i >> 10;                 // coalesced along k
        int row = (c >> 3) * HH + bk * 8 + (c & 7);
        Bs[k * 32 + c] = Whh[(size_t)row * HH + k];
    }
    // Zero c-state and this CTA's slice of h buffer 0.
    for (int i = tid; i < 512; i += PTHREADS) {
        Cs[i] = 0.f;
        int b = i >> 3, jj = i & 7;
        g_h[0][b * HH + bk * 8 + jj] = 0.f;
    }
    __threadfence();
    grid_barrier();

    const int grp  = tid >> 7;       // K-split group: 0 or 1
    const int ltid = tid & 127;
    const int tm   = ltid >> 3;      // 0..15 -> m = tm*4
    const int tn   = ltid & 7;       // 0..7  -> c = tn*4
    float* As = smem + OFF_AS + grp * (32 * PAS);

    for (int t = 0; t < TT; ++t) {
        const float* hprev = g_h[t & 1];

        float acc[4][4];
#pragma unroll
        for (int i = 0; i < 4; i++)
#pragma unroll
            for (int j = 0; j < 4; j++) acc[i][j] = 0.f;

        // GEMM over this group's half of K (512), in 16 chunks of 32.
        for (int ch = 0; ch < 16; ++ch) {
            const int kbase = grp * 512 + ch * 32;
            __syncthreads();
#pragma unroll
            for (int i = 0; i < 4; i++) {
                int s = ltid + i * 128; int r = s >> 3, cc = s & 7;
                float4 v = *reinterpret_cast<const float4*>(
                    hprev + (size_t)r * HH + kbase + cc * 4);
                As[(cc * 4 + 0) * PAS + r] = v.x;
                As[(cc * 4 + 1) * PAS + r] = v.y;
                As[(cc * 4 + 2) * PAS + r] = v.z;
                As[(cc * 4 + 3) * PAS + r] = v.w;
            }
            __syncthreads();
#pragma unroll
            for (int kk = 0; kk < 32; kk++) {
                float4 av = *reinterpret_cast<const float4*>(As + kk * PAS + tm * 4);
                float4 bv = *reinterpret_cast<const float4*>(Bs + (kbase + kk) * 32 + tn * 4);
                float a4[4] = {av.x, av.y, av.z, av.w};
                float b4[4] = {bv.x, bv.y, bv.z, bv.w};
#pragma unroll
                for (int i = 0; i < 4; i++)
#pragma unroll
                    for (int j = 0; j < 4; j++)
                        acc[i][j] += a4[i] * b4[j];
            }
        }

        // K-split reduction: group 1 -> smem, group 0 adds.
        __syncthreads();
        if (grp == 1) {
#pragma unroll
            for (int i = 0; i < 4; i++)
                *reinterpret_cast<float4*>(Red + (tm * 4 + i) * 32 + tn * 4) =
                    make_float4(acc[i][0], acc[i][1], acc[i][2], acc[i][3]);
        }
        __syncthreads();
        if (grp == 0) {
            const int g   = tn >> 1;          // gate of this thread's 4 cols
            const int jj0 = (tn & 1) * 4;
            const int gcol = g * HH + bk * 8 + jj0;   // global gate column
#pragma unroll
            for (int i = 0; i < 4; i++) {
                const int b = tm * 4 + i;
                float4 r = *reinterpret_cast<const float4*>(
                    Red + b * 32 + tn * 4);
                float4 xp = *reinterpret_cast<const float4*>(
                    &g_xproj[(size_t)(t * BB + b) * GG + gcol]);
                float4 v = make_float4(acc[i][0] + r.x + xp.x,
                                       acc[i][1] + r.y + xp.y,
                                       acc[i][2] + r.z + xp.z,
                                       acc[i][3] + r.w + xp.w);
                *reinterpret_cast<float4*>(Gs + g * 512 + b * 8 + jj0) = v;
            }
        }
        __syncthreads();

        // Pointwise cell update for this CTA's 64x8 (b, jj) block.
        float* hnext = g_h[(t + 1) & 1];
        for (int p = tid; p < 512; p += PTHREADS) {
            int b = p >> 3, jj = p & 7;
            float gi = sigf(Gs[p]);             // gate i
            float gf = sigf(Gs[512 + p]);       // gate f
            float gg = tanhf(Gs[1024 + p]);     // gate g
            float go = sigf(Gs[1536 + p]);      // gate o
            float c  = gf * Cs[p] + gi * gg;
            Cs[p] = c;
            float h = go * tanhf(c);
            int col = bk * 8 + jj;
            out[(size_t)t * BB * HH + b * HH + col] = h;
            hnext[b * HH + col] = h;
            if (t == TT - 1) {
                out[(size_t)TT * BB * HH + b * HH + col] = h;            // h tail
                out[(size_t)TT * BB * HH + BB * HH + b * HH + col] = c;  // c tail
            }
        }
        __threadfence();
        grid_barrier();
    }
}

// ---------------------------------------------------------------------------
// kernel_launch: exactly 2 graph nodes.
// Inputs: x, W_ih, W_hh, b_ih, b_hh (metadata order). Output fp32:
//   [ outputs (T*B*H) | h (B*H) | c (B*H) ]
// ---------------------------------------------------------------------------
extern "C" void kernel_launch(void* const* d_in, const int* in_sizes, int n_in,
                              void* d_out, int out_size)
{
    const float* x    = (const float*)d_in[0];
    const float* W_ih = (const float*)d_in[1];
    const float* W_hh = (const float*)d_in[2];
    const float* b_ih = (const float*)d_in[3];
    const float* b_hh = (const float*)d_in[4];
    float* out = (float*)d_out;
    (void)in_sizes; (void)n_in; (void)out_size;

    cudaFuncSetAttribute(lstm_persist,
                         cudaFuncAttributeMaxDynamicSharedMemorySize,
                         SMEM_BYTES);

    dim3 xgrid(GG / 64, (TT * BB) / 64);
    xproj_gemm<<<xgrid, 256>>>(x, W_ih, b_ih, b_hh);
    lstm_persist<<<NCTA, PTHREADS, SMEM_BYTES>>>(W_hh, out);
}